// round 3
// baseline (speedup 1.0000x reference)
#include <cuda_runtime.h>
#include <cuda_bf16.h>
#include <math.h>

// ---------------------------------------------------------------------------
// FARGAN: 100 frames x 4 subframes recurrent vocoder, B=64.
// Phase A: frame conv (Wc1,Wc2,Wc3) hoisted out of the sequential loop as
//          3 tiled fp32 GEMMs over a packed (6400 x 256) matrix.
// Phase B: persistent recurrent kernel: 32 CTAs x 384 threads, 2 batch
//          chains per CTA, all state in SMEM, weights streamed from L2.
// ---------------------------------------------------------------------------

#define FRN 100
#define NBATCH 64

// Scratch (device globals: allocation-free rule)
__device__ float g_X [6400 * 256];
__device__ float g_H1[6400 * 256];
__device__ float g_H2[6400 * 256];
__device__ float g_C [6400 * 512];
__device__ int   g_P [6400];

// ---------------------------------------------------------------------------
// Pack kernel: X[m=b*100+t, 0:192] = features[b, 0:192, t]; X[m,192:256]=global[b]
// Also extracts integer pitch period per (b,t).
// ---------------------------------------------------------------------------
__global__ void pack_kernel(const float* __restrict__ feats,
                            const float* __restrict__ gf)
{
    int m = blockIdx.x;              // b*100 + t
    int b = m / FRN, t = m % FRN;
    int c = threadIdx.x;             // 0..255
    float v;
    if (c < 192) v = feats[b * 193 * FRN + c * FRN + t];
    else         v = gf[b * 64 + (c - 192)];
    g_X[m * 256 + c] = v;
    if (c == 0)
        g_P[m] = (int)rintf(feats[b * 193 * FRN + 192 * FRN + t]);
}

// ---------------------------------------------------------------------------
// Tiled NT GEMM with fused tanh: C[m,n] = tanh( sum_k A[m,k] * W[n,k] )
// A: MxK row-major, W: NxK row-major. BM=BN=64, BK=16, 256 thr, 4x4 microtile.
// M,N,K all divisible by tile sizes for our shapes.
// ---------------------------------------------------------------------------
#define GBM 64
#define GBN 64
#define GBK 16
__global__ __launch_bounds__(256) void gemm_nt_tanh(
    const float* __restrict__ A, const float* __restrict__ W,
    float* __restrict__ C, int M, int N, int K)
{
    __shared__ float As[GBK][GBM];
    __shared__ float Ws[GBK][GBN];
    const int tid = threadIdx.x;
    const int tx = tid & 15, ty = tid >> 4;
    const int row0 = blockIdx.y * GBM;
    const int col0 = blockIdx.x * GBN;

    float acc[4][4] = {};
    for (int k0 = 0; k0 < K; k0 += GBK) {
        #pragma unroll
        for (int i = tid; i < GBM * GBK; i += 256) {
            int r = i / GBK, kk = i % GBK;
            As[kk][r] = A[(row0 + r) * K + k0 + kk];
            Ws[kk][r] = W[(col0 + r) * K + k0 + kk];
        }
        __syncthreads();
        #pragma unroll
        for (int kk = 0; kk < GBK; kk++) {
            float4 a4 = *reinterpret_cast<const float4*>(&As[kk][ty * 4]);
            float4 b4 = *reinterpret_cast<const float4*>(&Ws[kk][tx * 4]);
            float a[4] = {a4.x, a4.y, a4.z, a4.w};
            float bv[4] = {b4.x, b4.y, b4.z, b4.w};
            #pragma unroll
            for (int i = 0; i < 4; i++)
                #pragma unroll
                for (int j = 0; j < 4; j++)
                    acc[i][j] = fmaf(a[i], bv[j], acc[i][j]);
        }
        __syncthreads();
    }
    #pragma unroll
    for (int i = 0; i < 4; i++)
        #pragma unroll
        for (int j = 0; j < 4; j++)
            C[(size_t)(row0 + ty * 4 + i) * N + col0 + tx * 4 + j] = tanhf(acc[i][j]);
}

// ---------------------------------------------------------------------------
// Recurrent kernel
// ---------------------------------------------------------------------------
__device__ __forceinline__ float sigm(float x) { return 1.0f / (1.0f + expf(-x)); }

template <int N>
__device__ __forceinline__ float dotN(const float* __restrict__ w, const float* x)
{
    const float4* w4 = reinterpret_cast<const float4*>(w);
    const float4* x4 = reinterpret_cast<const float4*>(x);
    float a0 = 0.f, a1 = 0.f, a2 = 0.f, a3 = 0.f;
    #pragma unroll 8
    for (int i = 0; i < N / 4; i++) {
        float4 wv = w4[i];
        float4 xv = x4[i];
        a0 = fmaf(wv.x, xv.x, a0);
        a1 = fmaf(wv.y, xv.y, a1);
        a2 = fmaf(wv.z, xv.z, a2);
        a3 = fmaf(wv.w, xv.w, a3);
    }
    return (a0 + a1) + (a2 + a3);
}

struct __align__(16) BState {
    float prev[512];   // sample ring buffer
    float v[388];      // [feat2s(128) | prev_sub(64) | lookback(68) | sfw(128)]
    float sfw[128];
    float xg[128];     // GRU input [fw/o1/o2 | prev_sub]
    float gi[192];
    float gh[192];
    float sk[320];     // [o1 | o2 | o3 | fw | prev_sub]
    float sd[128];
    float so[128];
    float s1[64];
    float s2[64];
    float s3[64];
    float tmp[64];     // fw pre-GLU
};

__global__ __launch_bounds__(384, 1) void recur_kernel(
    const float* __restrict__ prev_in,
    const float* __restrict__ Wfw,  const float* __restrict__ Wfwg,
    const float* __restrict__ Wih1, const float* __restrict__ Whh1,
    const float* __restrict__ Wih2, const float* __restrict__ Whh2,
    const float* __restrict__ Wih3, const float* __restrict__ Whh3,
    const float* __restrict__ Wg1,  const float* __restrict__ Wg2,
    const float* __restrict__ Wg3,  const float* __restrict__ Wsg,
    const float* __restrict__ Wsd,  const float* __restrict__ Wout,
    float* __restrict__ outbuf)
{
    __shared__ BState sb[2];
    const int tid = threadIdx.x;
    const int b0 = blockIdx.x * 2;

    // init: previous samples + zero states
    for (int i = tid; i < 2 * 512; i += 384)
        sb[i >> 9].prev[i & 511] = prev_in[(b0 + (i >> 9)) * 512 + (i & 511)];
    for (int i = tid; i < 2 * 320; i += 384) {
        int b = i / 320, j = i % 320;
        if      (j < 64)  sb[b].s1[j]        = 0.f;
        else if (j < 128) sb[b].s2[j - 64]   = 0.f;
        else if (j < 192) sb[b].s3[j - 128]  = 0.f;
        else              sb[b].sfw[j - 192] = 0.f;
    }
    __syncthreads();

    for (int t = 0; t < FRN; t++) {
        const int p0 = g_P[(b0 + 0) * FRN + t];
        const int p1 = g_P[(b0 + 1) * FRN + t];
        for (int k = 0; k < 4; k++) {
            const int step = t * 4 + k;
            const int head = (step * 64) & 511;

            // --- Stage A: build Wfw input vector v, xg[64:128], sk[256:320]
            for (int i = tid; i < 2 * 388; i += 384) {
                const int b = (i >= 388);
                const int j = i - b * 388;
                BState& S = sb[b];
                const int p = b ? p1 : p0;
                float val;
                if (j < 128) {
                    val = g_C[(size_t)((b0 + b) * FRN + t) * 512 + 4 * j + k];
                } else if (j < 192) {
                    int jj = j - 128;
                    val = S.prev[(head + 448 + jj) & 511];   // prev_sub
                    S.xg[64 + jj] = val;
                    S.sk[256 + jj] = val;
                } else if (j < 260) {
                    int jj = j - 192;
                    int li = 510 - p + jj;
                    if (li >= 512) li -= p;
                    val = S.prev[(head + li) & 511];          // lookback
                } else {
                    val = S.sfw[j - 260];
                }
                S.v[j] = val;
            }
            __syncthreads();

            // --- Stage B: fw_pre = tanh(v @ Wfw.T)
            if (tid < 128) {
                int b = tid >> 6, r = tid & 63;
                sb[b].tmp[r] = tanhf(dotN<388>(Wfw + r * 388, sb[b].v));
            }
            __syncthreads();

            // --- Stage C: fw = GLU(fw_pre, Wfw_g)
            if (tid < 128) {
                int b = tid >> 6, r = tid & 63;
                float g = dotN<64>(Wfwg + r * 64, sb[b].tmp);
                float f = sb[b].tmp[r] * sigm(g);
                sb[b].sk[192 + r] = f;   // fw slot of skip
                sb[b].xg[r] = f;         // GRU1 input
            }
            __syncthreads();

            // --- 3 GRU + GLU blocks
            #pragma unroll
            for (int gr = 0; gr < 3; gr++) {
                const float* Wih = (gr == 0) ? Wih1 : (gr == 1) ? Wih2 : Wih3;
                const float* Whh = (gr == 0) ? Whh1 : (gr == 1) ? Whh2 : Whh3;
                const float* Wg  = (gr == 0) ? Wg1  : (gr == 1) ? Wg2  : Wg3;
                {
                    int b = tid / 192, r = tid % 192;
                    BState& S = sb[b];
                    const float* s = (gr == 0) ? S.s1 : (gr == 1) ? S.s2 : S.s3;
                    S.gi[r] = dotN<128>(Wih + r * 128, S.xg);
                    S.gh[r] = dotN<64>(Whh + r * 64, s);
                }
                __syncthreads();
                if (tid < 128) {
                    int b = tid >> 6, j = tid & 63;
                    BState& S = sb[b];
                    float* s = (gr == 0) ? S.s1 : (gr == 1) ? S.s2 : S.s3;
                    float r_ = sigm(S.gi[j] + S.gh[j]);
                    float z  = sigm(S.gi[64 + j] + S.gh[64 + j]);
                    float n  = tanhf(S.gi[128 + j] + r_ * S.gh[128 + j]);
                    s[j] = (1.f - z) * n + z * s[j];
                }
                __syncthreads();
                if (tid < 128) {
                    int b = tid >> 6, j = tid & 63;
                    BState& S = sb[b];
                    const float* s = (gr == 0) ? S.s1 : (gr == 1) ? S.s2 : S.s3;
                    float g = dotN<64>(Wg + j * 64, s);
                    float o = s[j] * sigm(g);
                    S.sk[gr * 64 + j] = o;
                    if (gr < 2) S.xg[j] = o;   // next GRU input
                }
                __syncthreads();
            }

            // --- sd = tanh(skip @ Wsd.T)
            if (tid < 256) {
                int b = tid >> 7, r = tid & 127;
                sb[b].sd[r] = tanhf(dotN<320>(Wsd + r * 320, sb[b].sk));
            }
            __syncthreads();

            // --- so = GLU(sd, Wsg)
            if (tid < 256) {
                int b = tid >> 7, r = tid & 127;
                float g = dotN<128>(Wsg + r * 128, sb[b].sd);
                sb[b].so[r] = sb[b].sd[r] * sigm(g);
            }
            __syncthreads();

            // --- out = tanh(so @ Wout.T); append to ring; sfw <- feat2s
            if (tid < 128) {
                int b = tid >> 6, r = tid & 63;
                float o = tanhf(dotN<128>(Wout + r * 128, sb[b].so));
                outbuf[(size_t)(b0 + b) * 25600 + (size_t)t * 256 + k * 64 + r] = o;
                sb[b].prev[(head + r) & 511] = o;
            }
            for (int i = tid; i < 256; i += 384) {
                int b = i >> 7, j = i & 127;
                sb[b].sfw[j] = sb[b].v[j];   // new sfw = current feat2s
            }
            __syncthreads();
        }
    }
}

// ---------------------------------------------------------------------------
extern "C" void kernel_launch(void* const* d_in, const int* in_sizes, int n_in,
                              void* d_out, int out_size)
{
    const float* features = (const float*)d_in[0];
    const float* gfeat    = (const float*)d_in[1];
    const float* prev     = (const float*)d_in[2];
    const float* Wc1      = (const float*)d_in[3];
    const float* Wc2      = (const float*)d_in[4];
    const float* Wc3      = (const float*)d_in[5];
    const float* Wfw      = (const float*)d_in[6];
    const float* Wfwg     = (const float*)d_in[7];
    const float* Wih1     = (const float*)d_in[8];
    const float* Whh1     = (const float*)d_in[9];
    const float* Wih2     = (const float*)d_in[10];
    const float* Whh2     = (const float*)d_in[11];
    const float* Wih3     = (const float*)d_in[12];
    const float* Whh3     = (const float*)d_in[13];
    const float* Wg1      = (const float*)d_in[14];
    const float* Wg2      = (const float*)d_in[15];
    const float* Wg3      = (const float*)d_in[16];
    const float* Wsg      = (const float*)d_in[17];
    const float* Wsd      = (const float*)d_in[18];
    const float* Wout     = (const float*)d_in[19];
    float* out = (float*)d_out;

    float *pX, *pH1, *pH2, *pC;
    cudaGetSymbolAddress((void**)&pX,  g_X);
    cudaGetSymbolAddress((void**)&pH1, g_H1);
    cudaGetSymbolAddress((void**)&pH2, g_H2);
    cudaGetSymbolAddress((void**)&pC,  g_C);

    // Phase A: frame-feature conv stack (not recurrent)
    pack_kernel<<<6400, 256>>>(features, gfeat);
    gemm_nt_tanh<<<dim3(4, 100), 256>>>(pX,  Wc1, pH1, 6400, 256, 256);
    gemm_nt_tanh<<<dim3(4, 100), 256>>>(pH1, Wc2, pH2, 6400, 256, 256);
    gemm_nt_tanh<<<dim3(8, 100), 256>>>(pH2, Wc3, pC,  6400, 512, 256);

    // Phase B: persistent recurrent kernel (2 batch chains per CTA)
    recur_kernel<<<32, 384>>>(prev,
                              Wfw, Wfwg,
                              Wih1, Whh1, Wih2, Whh2, Wih3, Whh3,
                              Wg1, Wg2, Wg3, Wsg, Wsd, Wout,
                              out);
}

// round 4
// speedup vs baseline: 4.1095x; 4.1095x over previous
#include <cuda_runtime.h>
#include <cuda_bf16.h>
#include <math.h>

// ---------------------------------------------------------------------------
// FARGAN: 100 frames x 4 subframes recurrent vocoder, B=64.
// Phase A: frame conv (Wc1,Wc2,Wc3) hoisted out of the sequential loop as
//          3 tiled fp32 GEMMs over a packed (6400 x 256) matrix.
// Phase P: weight repack into coalesced [K/4][Nout][4] layout.
// Phase B: persistent recurrent kernel: 32 CTAs x 384 threads, 2 batch
//          chains per CTA; coalesced weight streaming + split-K threading.
// ---------------------------------------------------------------------------

#define FRN 100

// Scratch (device globals: allocation-free rule)
__device__ float g_X [6400 * 256];
__device__ float g_H1[6400 * 256];
__device__ float g_H2[6400 * 256];
__device__ float g_C [6400 * 512];
__device__ int   g_P [6400];
__device__ float g_Wp[217344];   // packed recurrent weights

// Packed weight offsets (floats)
#define OFF_FW    0        // Wfw   64 x 388
#define OFF_FWG   24832    // Wfwg  64 x 64
#define OFF_IH1   28928    // Wih1 192 x 128
#define OFF_HH1   53504    // Whh1 192 x 64
#define OFF_IH2   65792
#define OFF_HH2   90368
#define OFF_IH3   102656
#define OFF_HH3   127232
#define OFF_G1    139520   // Wg 64 x 64
#define OFF_G2    143616
#define OFF_G3    147712
#define OFF_SD    151808   // Wsd 128 x 320
#define OFF_SG    192768   // Wsg 128 x 128
#define OFF_OUT   209152   // Wout 64 x 128

// ---------------------------------------------------------------------------
// Pack X matrix for the conv GEMMs + extract pitch periods.
// ---------------------------------------------------------------------------
__global__ void pack_kernel(const float* __restrict__ feats,
                            const float* __restrict__ gf)
{
    int m = blockIdx.x;              // b*100 + t
    int b = m / FRN, t = m % FRN;
    int c = threadIdx.x;             // 0..255
    float v;
    if (c < 192) v = feats[b * 193 * FRN + c * FRN + t];
    else         v = gf[b * 64 + (c - 192)];
    g_X[m * 256 + c] = v;
    if (c == 0)
        g_P[m] = (int)rintf(feats[b * 193 * FRN + 192 * FRN + t]);
}

// ---------------------------------------------------------------------------
// Weight repack: dst[(k4*Nout + r)*4 + c] = src[r*K + 4*k4 + c]
// ---------------------------------------------------------------------------
__global__ void pack_w_kernel(const float* __restrict__ src,
                              float* __restrict__ dst, int Nout, int K)
{
    int i = blockIdx.x * blockDim.x + threadIdx.x;
    if (i >= Nout * K) return;
    int r = i / K, k = i % K;
    int k4 = k >> 2, c = k & 3;
    dst[(k4 * Nout + r) * 4 + c] = src[i];
}

// ---------------------------------------------------------------------------
// Tiled NT GEMM with fused tanh: C[m,n] = tanh( sum_k A[m,k] * W[n,k] )
// ---------------------------------------------------------------------------
#define GBM 64
#define GBN 64
#define GBK 16
__global__ __launch_bounds__(256) void gemm_nt_tanh(
    const float* __restrict__ A, const float* __restrict__ W,
    float* __restrict__ C, int M, int N, int K)
{
    __shared__ float As[GBK][GBM];
    __shared__ float Ws[GBK][GBN];
    const int tid = threadIdx.x;
    const int tx = tid & 15, ty = tid >> 4;
    const int row0 = blockIdx.y * GBM;
    const int col0 = blockIdx.x * GBN;

    float acc[4][4] = {};
    for (int k0 = 0; k0 < K; k0 += GBK) {
        #pragma unroll
        for (int i = tid; i < GBM * GBK; i += 256) {
            int r = i / GBK, kk = i % GBK;
            As[kk][r] = A[(row0 + r) * K + k0 + kk];
            Ws[kk][r] = W[(col0 + r) * K + k0 + kk];
        }
        __syncthreads();
        #pragma unroll
        for (int kk = 0; kk < GBK; kk++) {
            float4 a4 = *reinterpret_cast<const float4*>(&As[kk][ty * 4]);
            float4 b4 = *reinterpret_cast<const float4*>(&Ws[kk][tx * 4]);
            float a[4] = {a4.x, a4.y, a4.z, a4.w};
            float bv[4] = {b4.x, b4.y, b4.z, b4.w};
            #pragma unroll
            for (int i = 0; i < 4; i++)
                #pragma unroll
                for (int j = 0; j < 4; j++)
                    acc[i][j] = fmaf(a[i], bv[j], acc[i][j]);
        }
        __syncthreads();
    }
    #pragma unroll
    for (int i = 0; i < 4; i++)
        #pragma unroll
        for (int j = 0; j < 4; j++)
            C[(size_t)(row0 + ty * 4 + i) * N + col0 + tx * 4 + j] = tanhf(acc[i][j]);
}

// ---------------------------------------------------------------------------
// Recurrent kernel helpers
// ---------------------------------------------------------------------------
__device__ __forceinline__ float sigm(float x) { return 1.0f / (1.0f + expf(-x)); }

// Partial dot over k4 in [k0, k0+cnt) for row r of packed weight (NOUT rows),
// simultaneously for both batch activation vectors. Coalesced: lanes with
// consecutive r read consecutive float4s.
template <int NOUT>
__device__ __forceinline__ void pdot2(const float4* __restrict__ W,
                                      const float* __restrict__ x0,
                                      const float* __restrict__ x1,
                                      int r, int k0, int cnt,
                                      float& out0, float& out1)
{
    const float4* x04 = reinterpret_cast<const float4*>(x0);
    const float4* x14 = reinterpret_cast<const float4*>(x1);
    float4 a0 = {0.f,0.f,0.f,0.f}, a1 = {0.f,0.f,0.f,0.f};
    #pragma unroll 4
    for (int k = k0; k < k0 + cnt; k++) {
        float4 w  = W[k * NOUT + r];
        float4 xa = x04[k];
        float4 xb = x14[k];
        a0.x = fmaf(w.x, xa.x, a0.x); a0.y = fmaf(w.y, xa.y, a0.y);
        a0.z = fmaf(w.z, xa.z, a0.z); a0.w = fmaf(w.w, xa.w, a0.w);
        a1.x = fmaf(w.x, xb.x, a1.x); a1.y = fmaf(w.y, xb.y, a1.y);
        a1.z = fmaf(w.z, xb.z, a1.z); a1.w = fmaf(w.w, xb.w, a1.w);
    }
    out0 = (a0.x + a0.y) + (a0.z + a0.w);
    out1 = (a1.x + a1.y) + (a1.z + a1.w);
}

// Full dot for one batch (small matrices; K4 compile-time).
template <int NOUT, int K4>
__device__ __forceinline__ float pdot1(const float4* __restrict__ W,
                                       const float* __restrict__ x, int r)
{
    const float4* x4 = reinterpret_cast<const float4*>(x);
    float4 a = {0.f,0.f,0.f,0.f};
    #pragma unroll 4
    for (int k = 0; k < K4; k++) {
        float4 w  = W[k * NOUT + r];
        float4 xv = x4[k];
        a.x = fmaf(w.x, xv.x, a.x); a.y = fmaf(w.y, xv.y, a.y);
        a.z = fmaf(w.z, xv.z, a.z); a.w = fmaf(w.w, xv.w, a.w);
    }
    return (a.x + a.y) + (a.z + a.w);
}

struct __align__(16) BS {
    float prev[512];   // sample ring buffer
    float v[388];      // [feat2s(128) | prev_sub(64) | lookback(68) | sfw(128)]
    float sfw[128];
    float xg[128];     // GRU input [cur(64) | prev_sub(64)]
    float st[3][64];   // GRU states
    float sk[320];     // [o1 | o2 | o3 | fw | prev_sub]
    float sd[128];
    float so[128];
    float tmp[64];     // fw pre-GLU
};

__global__ __launch_bounds__(384, 1) void recur_kernel(
    const float* __restrict__ prev_in,
    const float* __restrict__ Wp,
    float* __restrict__ outbuf)
{
    __shared__ BS sb[2];
    __shared__ float pbuf[2][6][192];
    const int tid = threadIdx.x;
    const int b0 = blockIdx.x * 2;

    const float4* Wfw  = (const float4*)(Wp + OFF_FW);
    const float4* Wfwg = (const float4*)(Wp + OFF_FWG);
    const float4* Wih[3] = {(const float4*)(Wp + OFF_IH1),
                            (const float4*)(Wp + OFF_IH2),
                            (const float4*)(Wp + OFF_IH3)};
    const float4* Whh[3] = {(const float4*)(Wp + OFF_HH1),
                            (const float4*)(Wp + OFF_HH2),
                            (const float4*)(Wp + OFF_HH3)};
    const float4* Wg[3]  = {(const float4*)(Wp + OFF_G1),
                            (const float4*)(Wp + OFF_G2),
                            (const float4*)(Wp + OFF_G3)};
    const float4* Wsd  = (const float4*)(Wp + OFF_SD);
    const float4* Wsg  = (const float4*)(Wp + OFF_SG);
    const float4* Wout = (const float4*)(Wp + OFF_OUT);

    // init: previous samples + zero states
    for (int i = tid; i < 2 * 512; i += 384)
        sb[i >> 9].prev[i & 511] = prev_in[(b0 + (i >> 9)) * 512 + (i & 511)];
    for (int i = tid; i < 2 * 320; i += 384) {
        int b = i / 320, j = i % 320;
        if      (j < 192) sb[b].st[j >> 6][j & 63] = 0.f;
        else              sb[b].sfw[j - 192] = 0.f;
    }
    __syncthreads();

    for (int t = 0; t < FRN; t++) {
        const int p0 = g_P[(b0 + 0) * FRN + t];
        const int p1 = g_P[(b0 + 1) * FRN + t];
        for (int k = 0; k < 4; k++) {
            const int step = t * 4 + k;
            const int head = (step * 64) & 511;

            // --- Stage A: build v, xg[64:128], sk[256:320]
            for (int i = tid; i < 2 * 388; i += 384) {
                const int b = (i >= 388);
                const int j = i - b * 388;
                BS& S = sb[b];
                const int p = b ? p1 : p0;
                float val;
                if (j < 128) {
                    val = g_C[(size_t)((b0 + b) * FRN + t) * 512 + 4 * j + k];
                } else if (j < 192) {
                    int jj = j - 128;
                    val = S.prev[(head + 448 + jj) & 511];   // prev_sub
                    S.xg[64 + jj] = val;
                    S.sk[256 + jj] = val;
                } else if (j < 260) {
                    int jj = j - 192;
                    int li = 510 - p + jj;
                    if (li >= 512) li -= p;
                    val = S.prev[(head + li) & 511];          // lookback
                } else {
                    val = S.sfw[j - 260];
                }
                S.v[j] = val;
            }
            __syncthreads();

            // --- Stage B: fw_pre partials = v @ Wfw.T  (K4=97, 6 slices)
            {
                int r = tid & 63, s = tid >> 6;
                int cnt = 16 + (s < 1);
                int k0 = s * 16 + (s >= 1 ? 1 : 0);
                float o0, o1;
                pdot2<64>(Wfw, sb[0].v, sb[1].v, r, k0, cnt, o0, o1);
                pbuf[0][s][r] = o0; pbuf[1][s][r] = o1;
            }
            __syncthreads();
            // reduce + tanh
            if (tid < 128) {
                int b = tid >> 6, r = tid & 63;
                float sum = 0.f;
                #pragma unroll
                for (int s = 0; s < 6; s++) sum += pbuf[b][s][r];
                sb[b].tmp[r] = tanhf(sum);
            }
            __syncthreads();
            // --- Stage C: fw = GLU(fw_pre, Wfw_g)
            if (tid < 128) {
                int b = tid >> 6, r = tid & 63;
                float g = pdot1<64, 16>(Wfwg, sb[b].tmp, r);
                float f = sb[b].tmp[r] * sigm(g);
                sb[b].sk[192 + r] = f;
                sb[b].xg[r] = f;
            }
            __syncthreads();

            // --- 3 GRU + GLU blocks
            #pragma unroll
            for (int gr = 0; gr < 3; gr++) {
                if (tid < 192) {
                    int r = tid;
                    float o0, o1;
                    pdot2<192>(Wih[gr], sb[0].xg, sb[1].xg, r, 0, 32, o0, o1);
                    pbuf[0][0][r] = o0; pbuf[1][0][r] = o1;
                } else {
                    int r = tid - 192;
                    float o0, o1;
                    pdot2<192>(Whh[gr], sb[0].st[gr], sb[1].st[gr], r, 0, 16, o0, o1);
                    pbuf[0][1][r] = o0; pbuf[1][1][r] = o1;
                }
                __syncthreads();
                if (tid < 128) {
                    int b = tid >> 6, j = tid & 63;
                    float r_ = sigm(pbuf[b][0][j]       + pbuf[b][1][j]);
                    float z  = sigm(pbuf[b][0][64 + j]  + pbuf[b][1][64 + j]);
                    float n  = tanhf(pbuf[b][0][128 + j] + r_ * pbuf[b][1][128 + j]);
                    sb[b].st[gr][j] = (1.f - z) * n + z * sb[b].st[gr][j];
                }
                __syncthreads();
                if (tid < 128) {
                    int b = tid >> 6, j = tid & 63;
                    float g = pdot1<64, 16>(Wg[gr], sb[b].st[gr], j);
                    float o = sb[b].st[gr][j] * sigm(g);
                    sb[b].sk[gr * 64 + j] = o;
                    if (gr < 2) sb[b].xg[j] = o;
                }
                __syncthreads();
            }

            // --- sd partials: skip @ Wsd.T  (K4=80, 3 slices)
            {
                int r = tid & 127, s = tid >> 7;
                int cnt = 26 + (s < 2);
                int k0 = s * 26 + (s < 2 ? s : 2);
                float o0, o1;
                pdot2<128>(Wsd, sb[0].sk, sb[1].sk, r, k0, cnt, o0, o1);
                pbuf[0][s][r] = o0; pbuf[1][s][r] = o1;
            }
            __syncthreads();
            if (tid < 256) {
                int b = tid >> 7, r = tid & 127;
                sb[b].sd[r] = tanhf(pbuf[b][0][r] + pbuf[b][1][r] + pbuf[b][2][r]);
            }
            __syncthreads();
            // --- so = GLU(sd, Wsg)  (K4=32, 3 slices)
            {
                int r = tid & 127, s = tid >> 7;
                int cnt = 10 + (s < 2);
                int k0 = s * 10 + (s < 2 ? s : 2);
                float o0, o1;
                pdot2<128>(Wsg, sb[0].sd, sb[1].sd, r, k0, cnt, o0, o1);
                pbuf[0][s][r] = o0; pbuf[1][s][r] = o1;
            }
            __syncthreads();
            if (tid < 256) {
                int b = tid >> 7, r = tid & 127;
                float g = pbuf[b][0][r] + pbuf[b][1][r] + pbuf[b][2][r];
                sb[b].so[r] = sb[b].sd[r] * sigm(g);
            }
            __syncthreads();
            // --- out = tanh(so @ Wout.T)  (K4=32, 6 slices)
            {
                int r = tid & 63, s = tid >> 6;
                int cnt = 5 + (s < 2);
                int k0 = s * 5 + (s < 2 ? s : 2);
                float o0, o1;
                pdot2<64>(Wout, sb[0].so, sb[1].so, r, k0, cnt, o0, o1);
                pbuf[0][s][r] = o0; pbuf[1][s][r] = o1;
            }
            __syncthreads();
            if (tid < 128) {
                int b = tid >> 6, r = tid & 63;
                float sum = 0.f;
                #pragma unroll
                for (int s = 0; s < 6; s++) sum += pbuf[b][s][r];
                float o = tanhf(sum);
                outbuf[(size_t)(b0 + b) * 25600 + (size_t)t * 256 + k * 64 + r] = o;
                sb[b].prev[(head + r) & 511] = o;
            }
            // sfw <- feat2s (v[0:128])
            for (int i = tid; i < 256; i += 384) {
                int b = i >> 7, j = i & 127;
                sb[b].sfw[j] = sb[b].v[j];
            }
            __syncthreads();
        }
    }
}

// ---------------------------------------------------------------------------
extern "C" void kernel_launch(void* const* d_in, const int* in_sizes, int n_in,
                              void* d_out, int out_size)
{
    const float* features = (const float*)d_in[0];
    const float* gfeat    = (const float*)d_in[1];
    const float* prev     = (const float*)d_in[2];
    const float* Wc1      = (const float*)d_in[3];
    const float* Wc2      = (const float*)d_in[4];
    const float* Wc3      = (const float*)d_in[5];
    float* out = (float*)d_out;

    float *pX, *pH1, *pH2, *pC, *pWp;
    cudaGetSymbolAddress((void**)&pX,  g_X);
    cudaGetSymbolAddress((void**)&pH1, g_H1);
    cudaGetSymbolAddress((void**)&pH2, g_H2);
    cudaGetSymbolAddress((void**)&pC,  g_C);
    cudaGetSymbolAddress((void**)&pWp, g_Wp);

    // Phase P: repack recurrent weights into coalesced layout
    struct PW { int idx, off, nout, K; };
    const PW pw[14] = {
        { 6, OFF_FW,  64, 388}, { 7, OFF_FWG, 64,  64},
        { 8, OFF_IH1, 192, 128}, { 9, OFF_HH1, 192, 64},
        {10, OFF_IH2, 192, 128}, {11, OFF_HH2, 192, 64},
        {12, OFF_IH3, 192, 128}, {13, OFF_HH3, 192, 64},
        {14, OFF_G1,  64,  64}, {15, OFF_G2,  64,  64}, {16, OFF_G3, 64, 64},
        {17, OFF_SG, 128, 128}, {18, OFF_SD, 128, 320}, {19, OFF_OUT, 64, 128},
    };
    for (int i = 0; i < 14; i++) {
        int n = pw[i].nout * pw[i].K;
        pack_w_kernel<<<(n + 255) / 256, 256>>>((const float*)d_in[pw[i].idx],
                                                pWp + pw[i].off,
                                                pw[i].nout, pw[i].K);
    }

    // Phase A: frame-feature conv stack (not recurrent)
    pack_kernel<<<6400, 256>>>(features, gfeat);
    gemm_nt_tanh<<<dim3(4, 100), 256>>>(pX,  Wc1, pH1, 6400, 256, 256);
    gemm_nt_tanh<<<dim3(4, 100), 256>>>(pH1, Wc2, pH2, 6400, 256, 256);
    gemm_nt_tanh<<<dim3(8, 100), 256>>>(pH2, Wc3, pC,  6400, 512, 256);

    // Phase B: persistent recurrent kernel (2 batch chains per CTA)
    recur_kernel<<<32, 384>>>(prev, pWp, out);
}

// round 5
// speedup vs baseline: 4.4319x; 1.0785x over previous
#include <cuda_runtime.h>
#include <cuda_bf16.h>
#include <math.h>

// ---------------------------------------------------------------------------
// FARGAN: 100 frames x 4 subframes recurrent vocoder, B=64.
// Phase A: frame conv hoisted out of the sequential loop (3 fp32 GEMMs).
// Phase P: weight repack into coalesced [K/4][Nout][4] layout.
// Phase B: persistent recurrent kernel: 32 CTAs x 512 threads, 2 batch
//          chains per CTA; small weight matrices cached in SMEM, large ones
//          streamed from L2 with wide split-K threading.
// ---------------------------------------------------------------------------

#define FRN 100

// Scratch (device globals: allocation-free rule)
__device__ float g_X [6400 * 256];
__device__ float g_H1[6400 * 256];
__device__ float g_H2[6400 * 256];
__device__ float g_C [6400 * 512];
__device__ int   g_P [6400];
__device__ float g_Wp[217344];   // packed recurrent weights

// Packed weight offsets (floats)
#define OFF_FW    0        // Wfw   64 x 388
#define OFF_FWG   24832    // Wfwg  64 x 64
#define OFF_IH1   28928    // Wih1 192 x 128
#define OFF_HH1   53504    // Whh1 192 x 64
#define OFF_IH2   65792
#define OFF_HH2   90368
#define OFF_IH3   102656
#define OFF_HH3   127232
#define OFF_G1    139520   // Wg 64 x 64
#define OFF_G2    143616
#define OFF_G3    147712
#define OFF_SD    151808   // Wsd 128 x 320
#define OFF_SG    192768   // Wsg 128 x 128
#define OFF_OUT   209152   // Wout 64 x 128

// ---------------------------------------------------------------------------
__global__ void pack_kernel(const float* __restrict__ feats,
                            const float* __restrict__ gf)
{
    int m = blockIdx.x;              // b*100 + t
    int b = m / FRN, t = m % FRN;
    int c = threadIdx.x;             // 0..255
    float v;
    if (c < 192) v = feats[b * 193 * FRN + c * FRN + t];
    else         v = gf[b * 64 + (c - 192)];
    g_X[m * 256 + c] = v;
    if (c == 0)
        g_P[m] = (int)rintf(feats[b * 193 * FRN + 192 * FRN + t]);
}

__global__ void pack_w_kernel(const float* __restrict__ src,
                              float* __restrict__ dst, int Nout, int K)
{
    int i = blockIdx.x * blockDim.x + threadIdx.x;
    if (i >= Nout * K) return;
    int r = i / K, k = i % K;
    int k4 = k >> 2, c = k & 3;
    dst[(k4 * Nout + r) * 4 + c] = src[i];
}

// ---------------------------------------------------------------------------
// Tiled NT GEMM with fused tanh
// ---------------------------------------------------------------------------
#define GBM 64
#define GBN 64
#define GBK 16
__global__ __launch_bounds__(256) void gemm_nt_tanh(
    const float* __restrict__ A, const float* __restrict__ W,
    float* __restrict__ C, int M, int N, int K)
{
    __shared__ float As[GBK][GBM];
    __shared__ float Ws[GBK][GBN];
    const int tid = threadIdx.x;
    const int tx = tid & 15, ty = tid >> 4;
    const int row0 = blockIdx.y * GBM;
    const int col0 = blockIdx.x * GBN;

    float acc[4][4] = {};
    for (int k0 = 0; k0 < K; k0 += GBK) {
        #pragma unroll
        for (int i = tid; i < GBM * GBK; i += 256) {
            int r = i / GBK, kk = i % GBK;
            As[kk][r] = A[(row0 + r) * K + k0 + kk];
            Ws[kk][r] = W[(col0 + r) * K + k0 + kk];
        }
        __syncthreads();
        #pragma unroll
        for (int kk = 0; kk < GBK; kk++) {
            float4 a4 = *reinterpret_cast<const float4*>(&As[kk][ty * 4]);
            float4 b4 = *reinterpret_cast<const float4*>(&Ws[kk][tx * 4]);
            float a[4] = {a4.x, a4.y, a4.z, a4.w};
            float bv[4] = {b4.x, b4.y, b4.z, b4.w};
            #pragma unroll
            for (int i = 0; i < 4; i++)
                #pragma unroll
                for (int j = 0; j < 4; j++)
                    acc[i][j] = fmaf(a[i], bv[j], acc[i][j]);
        }
        __syncthreads();
    }
    #pragma unroll
    for (int i = 0; i < 4; i++)
        #pragma unroll
        for (int j = 0; j < 4; j++)
            C[(size_t)(row0 + ty * 4 + i) * N + col0 + tx * 4 + j] = tanhf(acc[i][j]);
}

// ---------------------------------------------------------------------------
// Recurrent kernel helpers
// ---------------------------------------------------------------------------
__device__ __forceinline__ float sigm(float x) { return 1.0f / (1.0f + expf(-x)); }

// Partial dot over k4 in [k0,k0+cnt) of packed weight row r (NOUT rows),
// simultaneously for both batch activation vectors.
template <int NOUT>
__device__ __forceinline__ void pdot2(const float4* __restrict__ W,
                                      const float* __restrict__ x0,
                                      const float* __restrict__ x1,
                                      int r, int k0, int cnt,
                                      float& out0, float& out1)
{
    const float4* x04 = reinterpret_cast<const float4*>(x0);
    const float4* x14 = reinterpret_cast<const float4*>(x1);
    float4 a0 = {0.f,0.f,0.f,0.f}, a1 = {0.f,0.f,0.f,0.f};
    #pragma unroll 4
    for (int k = k0; k < k0 + cnt; k++) {
        float4 w  = W[k * NOUT + r];
        float4 xa = x04[k];
        float4 xb = x14[k];
        a0.x = fmaf(w.x, xa.x, a0.x); a0.y = fmaf(w.y, xa.y, a0.y);
        a0.z = fmaf(w.z, xa.z, a0.z); a0.w = fmaf(w.w, xa.w, a0.w);
        a1.x = fmaf(w.x, xb.x, a1.x); a1.y = fmaf(w.y, xb.y, a1.y);
        a1.z = fmaf(w.z, xb.z, a1.z); a1.w = fmaf(w.w, xb.w, a1.w);
    }
    out0 = (a0.x + a0.y) + (a0.z + a0.w);
    out1 = (a1.x + a1.y) + (a1.z + a1.w);
}

// Full dot (one batch), compile-time K4.
template <int NOUT, int K4>
__device__ __forceinline__ float pdot1(const float4* __restrict__ W,
                                       const float* __restrict__ x, int r)
{
    const float4* x4 = reinterpret_cast<const float4*>(x);
    float4 a = {0.f,0.f,0.f,0.f};
    #pragma unroll 4
    for (int k = 0; k < K4; k++) {
        float4 w  = W[k * NOUT + r];
        float4 xv = x4[k];
        a.x = fmaf(w.x, xv.x, a.x); a.y = fmaf(w.y, xv.y, a.y);
        a.z = fmaf(w.z, xv.z, a.z); a.w = fmaf(w.w, xv.w, a.w);
    }
    return (a.x + a.y) + (a.z + a.w);
}

struct __align__(16) BS {
    float prev[512];   // sample ring buffer
    float v[388];      // [feat2s(128) | prev_sub(64) | lookback(68) | sfw(128)]
    float sfw[128];
    float xg[128];     // GRU input [cur(64) | prev_sub(64)]
    float st[3][64];   // GRU states
    float sk[320];     // [o1 | o2 | o3 | fw | prev_sub]
    float sd[128];
    float so[128];
    float tmp[64];     // fw pre-GLU
};

// Dynamic SMEM layout
struct __align__(16) SM {
    float wfwg[64 * 64];        // 16 KB
    float wg[3][64 * 64];       // 48 KB
    float wout[64 * 128];       // 32 KB
    float wsg[128 * 128];       // 64 KB
    BS    sb[2];
    float pb[2][1024];          // split-K partial buffers
};

__global__ __launch_bounds__(512, 1) void recur_kernel(
    const float* __restrict__ prev_in,
    const float* __restrict__ Wp,
    float* __restrict__ outbuf)
{
    extern __shared__ unsigned char smem_raw[];
    SM& SL = *reinterpret_cast<SM*>(smem_raw);

    const int tid = threadIdx.x;
    const int b0 = blockIdx.x * 2;

    const float4* Wfw  = (const float4*)(Wp + OFF_FW);
    const float4* Wih[3] = {(const float4*)(Wp + OFF_IH1),
                            (const float4*)(Wp + OFF_IH2),
                            (const float4*)(Wp + OFF_IH3)};
    const float4* Whh[3] = {(const float4*)(Wp + OFF_HH1),
                            (const float4*)(Wp + OFF_HH2),
                            (const float4*)(Wp + OFF_HH3)};
    const float4* Wsd  = (const float4*)(Wp + OFF_SD);

    // One-time: copy small weight matrices into SMEM (packed layout preserved)
    {
        const float4* src = (const float4*)(Wp + OFF_FWG);       // Wfwg..end is
        float4*       dst = (float4*)SL.wfwg;                    // contiguous?
        // Wfwg(4096) + nothing contiguous after it in our layout; copy per-matrix.
        for (int i = tid; i < 1024; i += 512) dst[i] = src[i];
        for (int m = 0; m < 3; m++) {
            const float4* s2 = (const float4*)(Wp + (m == 0 ? OFF_G1 : m == 1 ? OFF_G2 : OFF_G3));
            float4* d2 = (float4*)SL.wg[m];
            for (int i = tid; i < 1024; i += 512) d2[i] = s2[i];
        }
        const float4* s3 = (const float4*)(Wp + OFF_OUT);
        float4* d3 = (float4*)SL.wout;
        for (int i = tid; i < 2048; i += 512) d3[i] = s3[i];
        const float4* s4 = (const float4*)(Wp + OFF_SG);
        float4* d4 = (float4*)SL.wsg;
        for (int i = tid; i < 4096; i += 512) d4[i] = s4[i];
    }

    // init: previous samples + zero states
    for (int i = tid; i < 2 * 512; i += 512)
        SL.sb[i >> 9].prev[i & 511] = prev_in[(b0 + (i >> 9)) * 512 + (i & 511)];
    for (int i = tid; i < 2 * 320; i += 512) {
        int b = i / 320, j = i % 320;
        if      (j < 192) SL.sb[b].st[j >> 6][j & 63] = 0.f;
        else              SL.sb[b].sfw[j - 192] = 0.f;
    }
    __syncthreads();

    const float4* WfwgS = (const float4*)SL.wfwg;
    const float4* WgS[3] = {(const float4*)SL.wg[0], (const float4*)SL.wg[1],
                            (const float4*)SL.wg[2]};
    const float4* WoutS = (const float4*)SL.wout;
    const float4* WsgS  = (const float4*)SL.wsg;

    for (int t = 0; t < FRN; t++) {
        const int p0 = g_P[(b0 + 0) * FRN + t];
        const int p1 = g_P[(b0 + 1) * FRN + t];
        for (int k = 0; k < 4; k++) {
            const int step = t * 4 + k;
            const int head = (step * 64) & 511;

            // --- Stage A: build v, xg[64:128], sk[256:320]
            for (int i = tid; i < 2 * 388; i += 512) {
                const int b = (i >= 388);
                const int j = i - b * 388;
                BS& S = SL.sb[b];
                const int p = b ? p1 : p0;
                float val;
                if (j < 128) {
                    val = g_C[(size_t)((b0 + b) * FRN + t) * 512 + 4 * j + k];
                } else if (j < 192) {
                    int jj = j - 128;
                    val = S.prev[(head + 448 + jj) & 511];   // prev_sub
                    S.xg[64 + jj] = val;
                    S.sk[256 + jj] = val;
                } else if (j < 260) {
                    int jj = j - 192;
                    int li = 510 - p + jj;
                    if (li >= 512) li -= p;
                    val = S.prev[(head + li) & 511];          // lookback
                } else {
                    val = S.sfw[j - 260];
                }
                S.v[j] = val;
            }
            __syncthreads();

            // --- Stage B: fw_pre partials = v @ Wfw.T (K4=97, 8 slices)
            {
                int r = tid & 63, s = tid >> 6;          // s: 0..7
                int cnt = 12 + (s == 0);
                int k0 = s * 12 + (s > 0);
                float o0, o1;
                pdot2<64>(Wfw, SL.sb[0].v, SL.sb[1].v, r, k0, cnt, o0, o1);
                SL.pb[0][s * 64 + r] = o0; SL.pb[1][s * 64 + r] = o1;
            }
            __syncthreads();
            if (tid < 128) {
                int b = tid >> 6, r = tid & 63;
                float sum = 0.f;
                #pragma unroll
                for (int s = 0; s < 8; s++) sum += SL.pb[b][s * 64 + r];
                SL.sb[b].tmp[r] = tanhf(sum);
            }
            __syncthreads();
            // --- Stage C: fw = GLU(fw_pre, Wfw_g) [SMEM weights]
            if (tid < 128) {
                int b = tid >> 6, r = tid & 63;
                float g = pdot1<64, 16>(WfwgS, SL.sb[b].tmp, r);
                float f = SL.sb[b].tmp[r] * sigm(g);
                SL.sb[b].sk[192 + r] = f;
                SL.sb[b].xg[r] = f;
            }
            __syncthreads();

            // --- 3 GRU + GLU blocks
            #pragma unroll
            for (int gr = 0; gr < 3; gr++) {
                if (tid < 384) {
                    // gi partials: 192 rows x 2 k-slices of 16
                    int r = tid % 192, s = tid / 192;
                    float o0, o1;
                    pdot2<192>(Wih[gr], SL.sb[0].xg, SL.sb[1].xg, r, s * 16, 16, o0, o1);
                    SL.pb[0][s * 192 + r] = o0; SL.pb[1][s * 192 + r] = o1;
                } else {
                    // gh: 192 rows by 128 threads (t2<64 does a second row)
                    int t2 = tid - 384;
                    float o0, o1;
                    pdot2<192>(Whh[gr], SL.sb[0].st[gr], SL.sb[1].st[gr], t2, 0, 16, o0, o1);
                    SL.pb[0][384 + t2] = o0; SL.pb[1][384 + t2] = o1;
                    if (t2 < 64) {
                        int r2 = 128 + t2;
                        pdot2<192>(Whh[gr], SL.sb[0].st[gr], SL.sb[1].st[gr], r2, 0, 16, o0, o1);
                        SL.pb[0][384 + r2] = o0; SL.pb[1][384 + r2] = o1;
                    }
                }
                __syncthreads();
                if (tid < 128) {
                    int b = tid >> 6, j = tid & 63;
                    float* pb = SL.pb[b];
                    float gir = pb[j]        + pb[192 + j];
                    float giz = pb[64 + j]   + pb[256 + j];
                    float gin = pb[128 + j]  + pb[320 + j];
                    float r_ = sigm(gir + pb[384 + j]);
                    float z  = sigm(giz + pb[384 + 64 + j]);
                    float n  = tanhf(gin + r_ * pb[384 + 128 + j]);
                    SL.sb[b].st[gr][j] = (1.f - z) * n + z * SL.sb[b].st[gr][j];
                }
                __syncthreads();
                if (tid < 128) {
                    int b = tid >> 6, j = tid & 63;
                    float g = pdot1<64, 16>(WgS[gr], SL.sb[b].st[gr], j);
                    float o = SL.sb[b].st[gr][j] * sigm(g);
                    SL.sb[b].sk[gr * 64 + j] = o;
                    if (gr < 2) SL.sb[b].xg[j] = o;
                }
                __syncthreads();
            }

            // --- sd partials: skip @ Wsd.T (K4=80, 4 slices of 20)
            {
                int r = tid & 127, s = tid >> 7;         // s: 0..3
                float o0, o1;
                pdot2<128>(Wsd, SL.sb[0].sk, SL.sb[1].sk, r, s * 20, 20, o0, o1);
                SL.pb[0][s * 128 + r] = o0; SL.pb[1][s * 128 + r] = o1;
            }
            __syncthreads();
            if (tid < 256) {
                int b = tid >> 7, r = tid & 127;
                float* pb = SL.pb[b];
                SL.sb[b].sd[r] = tanhf((pb[r] + pb[128 + r]) + (pb[256 + r] + pb[384 + r]));
            }
            __syncthreads();
            // --- so = GLU(sd, Wsg) [SMEM weights] (K4=32, 4 slices of 8)
            {
                int r = tid & 127, s = tid >> 7;
                float o0, o1;
                pdot2<128>(WsgS, SL.sb[0].sd, SL.sb[1].sd, r, s * 8, 8, o0, o1);
                SL.pb[0][s * 128 + r] = o0; SL.pb[1][s * 128 + r] = o1;
            }
            __syncthreads();
            if (tid < 256) {
                int b = tid >> 7, r = tid & 127;
                float* pb = SL.pb[b];
                float g = (pb[r] + pb[128 + r]) + (pb[256 + r] + pb[384 + r]);
                SL.sb[b].so[r] = SL.sb[b].sd[r] * sigm(g);
            }
            __syncthreads();
            // --- out = tanh(so @ Wout.T) [SMEM weights] (K4=32, 8 slices of 4)
            {
                int r = tid & 63, s = tid >> 6;          // s: 0..7
                float o0, o1;
                pdot2<64>(WoutS, SL.sb[0].so, SL.sb[1].so, r, s * 4, 4, o0, o1);
                SL.pb[0][s * 64 + r] = o0; SL.pb[1][s * 64 + r] = o1;
            }
            __syncthreads();
            if (tid < 128) {
                int b = tid >> 6, r = tid & 63;
                float sum = 0.f;
                #pragma unroll
                for (int s = 0; s < 8; s++) sum += SL.pb[b][s * 64 + r];
                float o = tanhf(sum);
                outbuf[(size_t)(b0 + b) * 25600 + (size_t)t * 256 + k * 64 + r] = o;
                SL.sb[b].prev[(head + r) & 511] = o;
            } else if (tid < 384) {
                // sfw <- feat2s (v[0:128])
                int i = tid - 128;
                int b = i >> 7, j = i & 127;
                SL.sb[b].sfw[j] = SL.sb[b].v[j];
            }
            __syncthreads();
        }
    }
}

// ---------------------------------------------------------------------------
extern "C" void kernel_launch(void* const* d_in, const int* in_sizes, int n_in,
                              void* d_out, int out_size)
{
    const float* features = (const float*)d_in[0];
    const float* gfeat    = (const float*)d_in[1];
    const float* prev     = (const float*)d_in[2];
    const float* Wc1      = (const float*)d_in[3];
    const float* Wc2      = (const float*)d_in[4];
    const float* Wc3      = (const float*)d_in[5];
    float* out = (float*)d_out;

    float *pX, *pH1, *pH2, *pC, *pWp;
    cudaGetSymbolAddress((void**)&pX,  g_X);
    cudaGetSymbolAddress((void**)&pH1, g_H1);
    cudaGetSymbolAddress((void**)&pH2, g_H2);
    cudaGetSymbolAddress((void**)&pC,  g_C);
    cudaGetSymbolAddress((void**)&pWp, g_Wp);

    // Phase P: repack recurrent weights into coalesced layout
    struct PW { int idx, off, nout, K; };
    const PW pw[14] = {
        { 6, OFF_FW,  64, 388}, { 7, OFF_FWG, 64,  64},
        { 8, OFF_IH1, 192, 128}, { 9, OFF_HH1, 192, 64},
        {10, OFF_IH2, 192, 128}, {11, OFF_HH2, 192, 64},
        {12, OFF_IH3, 192, 128}, {13, OFF_HH3, 192, 64},
        {14, OFF_G1,  64,  64}, {15, OFF_G2,  64,  64}, {16, OFF_G3, 64, 64},
        {17, OFF_SG, 128, 128}, {18, OFF_SD, 128, 320}, {19, OFF_OUT, 64, 128},
    };
    for (int i = 0; i < 14; i++) {
        int n = pw[i].nout * pw[i].K;
        pack_w_kernel<<<(n + 255) / 256, 256>>>((const float*)d_in[pw[i].idx],
                                                pWp + pw[i].off,
                                                pw[i].nout, pw[i].K);
    }

    // Phase A: frame-feature conv stack (not recurrent)
    pack_kernel<<<6400, 256>>>(features, gfeat);
    gemm_nt_tanh<<<dim3(4, 100), 256>>>(pX,  Wc1, pH1, 6400, 256, 256);
    gemm_nt_tanh<<<dim3(4, 100), 256>>>(pH1, Wc2, pH2, 6400, 256, 256);
    gemm_nt_tanh<<<dim3(8, 100), 256>>>(pH2, Wc3, pC,  6400, 512, 256);

    // Phase B: persistent recurrent kernel (2 batch chains per CTA)
    static const int SMEM_BYTES = (int)sizeof(SM);
    cudaFuncSetAttribute(recur_kernel,
                         cudaFuncAttributeMaxDynamicSharedMemorySize, SMEM_BYTES);
    recur_kernel<<<32, 512, SMEM_BYTES>>>(prev, pWp, out);
}

// round 6
// speedup vs baseline: 6.3196x; 1.4259x over previous
#include <cuda_runtime.h>
#include <cuda_bf16.h>
#include <math.h>

// ---------------------------------------------------------------------------
// FARGAN: 100 frames x 4 subframes recurrent vocoder, B=64.
// Phase A: frame conv hoisted out of the sequential loop (3 fp32 GEMMs).
// Phase P: weight repack into coalesced [K/4][Nout][4] layout.
// Phase B: persistent recurrent kernel: 64 CTAs x 512 threads, ONE batch
//          chain per CTA (halves the per-CTA FMA floor); state-dependent
//          matvecs (gh, gi_prev, sd_prev) hoisted into one mega-stage;
//          Wsd slices computed concurrently inside GRU stages.
// ---------------------------------------------------------------------------

#define FRN 100

// Scratch (device globals: allocation-free rule)
__device__ float g_X [6400 * 256];
__device__ float g_H1[6400 * 256];
__device__ float g_H2[6400 * 256];
__device__ float g_C [6400 * 512];
__device__ int   g_P [6400];
__device__ float g_Wp[217344];   // packed recurrent weights

// Packed weight offsets (floats)
#define OFF_FW    0        // Wfw   64 x 388
#define OFF_FWG   24832    // Wfwg  64 x 64
#define OFF_IH1   28928    // Wih1 192 x 128
#define OFF_HH1   53504    // Whh1 192 x 64
#define OFF_IH2   65792
#define OFF_HH2   90368
#define OFF_IH3   102656
#define OFF_HH3   127232
#define OFF_G1    139520   // Wg 64 x 64
#define OFF_G2    143616
#define OFF_G3    147712
#define OFF_SD    151808   // Wsd 128 x 320
#define OFF_SG    192768   // Wsg 128 x 128
#define OFF_OUT   209152   // Wout 64 x 128

// ---------------------------------------------------------------------------
__global__ void pack_kernel(const float* __restrict__ feats,
                            const float* __restrict__ gf)
{
    int m = blockIdx.x;              // b*100 + t
    int b = m / FRN, t = m % FRN;
    int c = threadIdx.x;             // 0..255
    float v;
    if (c < 192) v = feats[b * 193 * FRN + c * FRN + t];
    else         v = gf[b * 64 + (c - 192)];
    g_X[m * 256 + c] = v;
    if (c == 0)
        g_P[m] = (int)rintf(feats[b * 193 * FRN + 192 * FRN + t]);
}

__global__ void pack_w_kernel(const float* __restrict__ src,
                              float* __restrict__ dst, int Nout, int K)
{
    int i = blockIdx.x * blockDim.x + threadIdx.x;
    if (i >= Nout * K) return;
    int r = i / K, k = i % K;
    int k4 = k >> 2, c = k & 3;
    dst[(k4 * Nout + r) * 4 + c] = src[i];
}

// ---------------------------------------------------------------------------
// Tiled NT GEMM with fused tanh
// ---------------------------------------------------------------------------
#define GBM 64
#define GBN 64
#define GBK 16
__global__ __launch_bounds__(256) void gemm_nt_tanh(
    const float* __restrict__ A, const float* __restrict__ W,
    float* __restrict__ C, int M, int N, int K)
{
    __shared__ float As[GBK][GBM];
    __shared__ float Ws[GBK][GBN];
    const int tid = threadIdx.x;
    const int tx = tid & 15, ty = tid >> 4;
    const int row0 = blockIdx.y * GBM;
    const int col0 = blockIdx.x * GBN;

    float acc[4][4] = {};
    for (int k0 = 0; k0 < K; k0 += GBK) {
        #pragma unroll
        for (int i = tid; i < GBM * GBK; i += 256) {
            int r = i / GBK, kk = i % GBK;
            As[kk][r] = A[(row0 + r) * K + k0 + kk];
            Ws[kk][r] = W[(col0 + r) * K + k0 + kk];
        }
        __syncthreads();
        #pragma unroll
        for (int kk = 0; kk < GBK; kk++) {
            float4 a4 = *reinterpret_cast<const float4*>(&As[kk][ty * 4]);
            float4 b4 = *reinterpret_cast<const float4*>(&Ws[kk][tx * 4]);
            float a[4] = {a4.x, a4.y, a4.z, a4.w};
            float bv[4] = {b4.x, b4.y, b4.z, b4.w};
            #pragma unroll
            for (int i = 0; i < 4; i++)
                #pragma unroll
                for (int j = 0; j < 4; j++)
                    acc[i][j] = fmaf(a[i], bv[j], acc[i][j]);
        }
        __syncthreads();
    }
    #pragma unroll
    for (int i = 0; i < 4; i++)
        #pragma unroll
        for (int j = 0; j < 4; j++)
            C[(size_t)(row0 + ty * 4 + i) * N + col0 + tx * 4 + j] = tanhf(acc[i][j]);
}

// ---------------------------------------------------------------------------
// Recurrent kernel helpers
// ---------------------------------------------------------------------------
__device__ __forceinline__ float sigm(float x) { return 1.0f / (1.0f + expf(-x)); }

// Fixed-count partial dot: rows packed [k4][NOUT][4]; global k4 index matches
// the x vector's float4 index.
template <int CNT>
__device__ __forceinline__ float pdotf(const float4* __restrict__ W, int NOUT,
                                       const float* __restrict__ x, int r, int k0)
{
    const float4* x4 = reinterpret_cast<const float4*>(x);
    float4 a = {0.f,0.f,0.f,0.f};
    #pragma unroll
    for (int i = 0; i < CNT; i++) {
        int k = k0 + i;
        float4 w  = W[k * NOUT + r];
        float4 xv = x4[k];
        a.x = fmaf(w.x, xv.x, a.x); a.y = fmaf(w.y, xv.y, a.y);
        a.z = fmaf(w.z, xv.z, a.z); a.w = fmaf(w.w, xv.w, a.w);
    }
    return (a.x + a.y) + (a.z + a.w);
}

// Runtime-count version (Wfw slices: 12 or 13)
__device__ __forceinline__ float pdotr(const float4* __restrict__ W, int NOUT,
                                       const float* __restrict__ x, int r,
                                       int k0, int cnt)
{
    const float4* x4 = reinterpret_cast<const float4*>(x);
    float4 a = {0.f,0.f,0.f,0.f};
    #pragma unroll 4
    for (int k = k0; k < k0 + cnt; k++) {
        float4 w  = W[k * NOUT + r];
        float4 xv = x4[k];
        a.x = fmaf(w.x, xv.x, a.x); a.y = fmaf(w.y, xv.y, a.y);
        a.z = fmaf(w.z, xv.z, a.z); a.w = fmaf(w.w, xv.w, a.w);
    }
    return (a.x + a.y) + (a.z + a.w);
}

// Dynamic SMEM layout (~183 KB)
struct __align__(16) SM {
    // SMEM-cached small weights (packed layout preserved)
    float wfwg[4096];
    float wg[3][4096];
    float wout[8192];
    float wsg[16384];
    // per-chain state
    float prev[512];    // sample ring buffer
    float v[388];       // [feat2s(128) | prev_sub(64) | lookback(68) | sfw(128)]
    float sfw[128];
    float xg[128];      // GRU input [cur(64) | prev_sub(64)]
    float st[3][64];    // GRU states
    float sk[320];      // [o1 | o2 | o3 | fw | prev_sub]
    float sd[128];
    float so[128];
    float tmp[64];      // fw pre-GLU
    // partial buffers
    float pb_fw[512];       // Wfw slices; reused for SG (4x128) and OUT (8x64)
    float pb_gh[3][192];    // Whh @ st      (hoisted)
    float pb_gip[3][192];   // Wih[:,64:128] @ prev_sub (hoisted)
    float pb_gic[2][192];   // Wih[:,0:64] @ cur (2 k-slices)
    float pb_sd[6][128];    // Wsd partials: [0]=prev_sub [1]=fw [2]=o1 [3]=o2 [4,5]=o3
};

__global__ __launch_bounds__(512, 1) void recur_kernel(
    const float* __restrict__ prev_in,
    const float* __restrict__ Wp,
    float* __restrict__ outbuf)
{
    extern __shared__ unsigned char smem_raw[];
    SM& SL = *reinterpret_cast<SM*>(smem_raw);

    const int tid = threadIdx.x;
    const int b = blockIdx.x;

    const float4* Wfw4 = (const float4*)(Wp + OFF_FW);
    const float4* Wih4[3] = {(const float4*)(Wp + OFF_IH1),
                             (const float4*)(Wp + OFF_IH2),
                             (const float4*)(Wp + OFF_IH3)};
    const float4* Whh4[3] = {(const float4*)(Wp + OFF_HH1),
                             (const float4*)(Wp + OFF_HH2),
                             (const float4*)(Wp + OFF_HH3)};
    const float4* Wsd4 = (const float4*)(Wp + OFF_SD);

    // One-time: copy small weight matrices into SMEM
    {
        const float4* s1 = (const float4*)(Wp + OFF_FWG);
        float4* d1 = (float4*)SL.wfwg;
        for (int i = tid; i < 1024; i += 512) d1[i] = s1[i];
        #pragma unroll
        for (int m = 0; m < 3; m++) {
            const float4* s2 = (const float4*)(Wp + (m == 0 ? OFF_G1 : m == 1 ? OFF_G2 : OFF_G3));
            float4* d2 = (float4*)SL.wg[m];
            for (int i = tid; i < 1024; i += 512) d2[i] = s2[i];
        }
        const float4* s3 = (const float4*)(Wp + OFF_OUT);
        float4* d3 = (float4*)SL.wout;
        for (int i = tid; i < 2048; i += 512) d3[i] = s3[i];
        const float4* s4 = (const float4*)(Wp + OFF_SG);
        float4* d4 = (float4*)SL.wsg;
        for (int i = tid; i < 4096; i += 512) d4[i] = s4[i];
    }

    // init: previous samples + zero states
    SL.prev[tid & 511] = prev_in[b * 512 + (tid & 511)];
    if (tid < 320) {
        if (tid < 192) SL.st[tid >> 6][tid & 63] = 0.f;
        else           SL.sfw[tid - 192] = 0.f;
    }
    if (tid >= 384) SL.sfw[tid - 384 + 128 - 128] = SL.sfw[tid - 384]; // no-op keep
    if (tid < 128) SL.sfw[tid] = 0.f;
    __syncthreads();

    const float4* WfwgS = (const float4*)SL.wfwg;
    const float4* WgS[3] = {(const float4*)SL.wg[0], (const float4*)SL.wg[1],
                            (const float4*)SL.wg[2]};
    const float4* WoutS = (const float4*)SL.wout;
    const float4* WsgS  = (const float4*)SL.wsg;

    for (int t = 0; t < FRN; t++) {
        const int p = g_P[b * FRN + t];
        for (int k = 0; k < 4; k++) {
            const int step = t * 4 + k;
            const int head = (step * 64) & 511;

            // --- Stage A: build v, xg[64:128], sk[256:320]
            if (tid < 388) {
                const int j = tid;
                float val;
                if (j < 128) {
                    val = g_C[(size_t)(b * FRN + t) * 512 + 4 * j + k];
                } else if (j < 192) {
                    int jj = j - 128;
                    val = SL.prev[(head + 448 + jj) & 511];   // prev_sub
                    SL.xg[64 + jj] = val;
                    SL.sk[256 + jj] = val;
                } else if (j < 260) {
                    int jj = j - 192;
                    int li = 510 - p + jj;
                    if (li >= 512) li -= p;
                    val = SL.prev[(head + li) & 511];          // lookback
                } else {
                    val = SL.sfw[j - 260];
                }
                SL.v[j] = val;
            }
            __syncthreads();

            // --- Mega stage: Wfw slices + ALL state-dependent matvecs
            // part 1: Wfw (K4=97, 8 slices)
            {
                int s = tid >> 6, r = tid & 63;
                int cnt = 12 + (s == 0);
                int k0 = s * 12 + (s > 0);
                SL.pb_fw[s * 64 + r] = pdotr(Wfw4, 64, SL.v, r, k0, cnt);
            }
            // part 2: 1280 tasks of 16 k4-iters
            //   [0,576)    gh[gr][r]   = Whh[gr] @ st[gr]
            //   [576,1152) gip[gr][r]  = Wih[gr][:,64:128] @ prev_sub
            //   [1152,1280) sd_prev[r] = Wsd[:,256:320] @ prev_sub
            #pragma unroll
            for (int pass = 0; pass < 3; pass++) {
                int id = tid + pass * 512;
                if (id < 576) {
                    int gr = (id >= 384) ? 2 : (id >= 192) ? 1 : 0;
                    int r = id - gr * 192;
                    SL.pb_gh[gr][r] = pdotf<16>(Whh4[gr], 192, SL.st[gr], r, 0);
                } else if (id < 1152) {
                    int id2 = id - 576;
                    int gr = (id2 >= 384) ? 2 : (id2 >= 192) ? 1 : 0;
                    int r = id2 - gr * 192;
                    SL.pb_gip[gr][r] = pdotf<16>(Wih4[gr], 192, SL.xg, r, 16);
                } else if (id < 1280) {
                    int r = id - 1152;
                    SL.pb_sd[0][r] = pdotf<16>(Wsd4, 128, SL.sk, r, 64);
                }
            }
            __syncthreads();

            // --- fw reduce + tanh
            if (tid < 64) {
                float s = 0.f;
                #pragma unroll
                for (int i = 0; i < 8; i++) s += SL.pb_fw[i * 64 + tid];
                SL.tmp[tid] = tanhf(s);
            }
            __syncthreads();
            // --- fw = GLU(tmp, Wfw_g) [SMEM]
            if (tid < 64) {
                float g = pdotf<16>(WfwgS, 64, SL.tmp, tid, 0);
                float f = SL.tmp[tid] * sigm(g);
                SL.sk[192 + tid] = f;
                SL.xg[tid] = f;
            }
            __syncthreads();

            // --- 3 GRU + GLU blocks (gi_cur only; gh/gip precomputed)
            #pragma unroll
            for (int gr = 0; gr < 3; gr++) {
                if (tid < 384) {
                    int s = (tid >= 192), r = tid - s * 192;
                    SL.pb_gic[s][r] = pdotf<8>(Wih4[gr], 192, SL.xg, r, s * 8);
                } else {
                    // concurrent Wsd slice for the just-produced vector
                    int r = tid - 384;  // 0..127
                    int k0 = (gr == 0) ? 48 : (gr == 1) ? 0 : 16;
                    SL.pb_sd[1 + gr][r] = pdotf<16>(Wsd4, 128, SL.sk, r, k0);
                }
                __syncthreads();
                if (tid < 64) {
                    int j = tid;
                    float gir = SL.pb_gic[0][j]       + SL.pb_gic[1][j]       + SL.pb_gip[gr][j];
                    float giz = SL.pb_gic[0][64 + j]  + SL.pb_gic[1][64 + j]  + SL.pb_gip[gr][64 + j];
                    float gin = SL.pb_gic[0][128 + j] + SL.pb_gic[1][128 + j] + SL.pb_gip[gr][128 + j];
                    float r_ = sigm(gir + SL.pb_gh[gr][j]);
                    float z  = sigm(giz + SL.pb_gh[gr][64 + j]);
                    float n  = tanhf(gin + r_ * SL.pb_gh[gr][128 + j]);
                    SL.st[gr][j] = (1.f - z) * n + z * SL.st[gr][j];
                }
                __syncthreads();
                if (tid < 64) {
                    int j = tid;
                    float g = pdotf<16>(WgS[gr], 64, SL.st[gr], j, 0);
                    float o = SL.st[gr][j] * sigm(g);
                    SL.sk[gr * 64 + j] = o;
                    if (gr < 2) SL.xg[j] = o;
                }
                __syncthreads();
            }

            // --- Wsd final slice (o3) + reduce + tanh
            if (tid < 256) {
                int r = tid & 127, s = tid >> 7;
                SL.pb_sd[4 + s][r] = pdotf<8>(Wsd4, 128, SL.sk, r, 32 + s * 8);
            }
            __syncthreads();
            if (tid < 128) {
                float sum = ((SL.pb_sd[2][tid] + SL.pb_sd[3][tid]) +
                             (SL.pb_sd[4][tid] + SL.pb_sd[5][tid])) +
                            (SL.pb_sd[1][tid] + SL.pb_sd[0][tid]);
                SL.sd[tid] = tanhf(sum);
            }
            __syncthreads();

            // --- so = GLU(sd, Wsg) [SMEM] (4 slices of 8)
            {
                int r = tid & 127, s = tid >> 7;
                SL.pb_fw[s * 128 + r] = pdotf<8>(WsgS, 128, SL.sd, r, s * 8);
            }
            __syncthreads();
            if (tid < 128) {
                float g = (SL.pb_fw[tid] + SL.pb_fw[128 + tid]) +
                          (SL.pb_fw[256 + tid] + SL.pb_fw[384 + tid]);
                SL.so[tid] = SL.sd[tid] * sigm(g);
            }
            __syncthreads();

            // --- out = tanh(so @ Wout.T) [SMEM] (8 slices of 4)
            {
                int r = tid & 63, s = tid >> 6;
                SL.pb_fw[s * 64 + r] = pdotf<4>(WoutS, 64, SL.so, r, s * 4);
            }
            __syncthreads();
            if (tid < 64) {
                float sum = 0.f;
                #pragma unroll
                for (int i = 0; i < 8; i++) sum += SL.pb_fw[i * 64 + tid];
                float o = tanhf(sum);
                outbuf[(size_t)b * 25600 + (size_t)t * 256 + k * 64 + tid] = o;
                SL.prev[(head + tid) & 511] = o;
            } else if (tid < 192) {
                int j = tid - 64;
                SL.sfw[j] = SL.v[j];    // new sfw = current feat2s
            }
            __syncthreads();
        }
    }
}

// ---------------------------------------------------------------------------
extern "C" void kernel_launch(void* const* d_in, const int* in_sizes, int n_in,
                              void* d_out, int out_size)
{
    const float* features = (const float*)d_in[0];
    const float* gfeat    = (const float*)d_in[1];
    const float* prev     = (const float*)d_in[2];
    const float* Wc1      = (const float*)d_in[3];
    const float* Wc2      = (const float*)d_in[4];
    const float* Wc3      = (const float*)d_in[5];
    float* out = (float*)d_out;

    float *pX, *pH1, *pH2, *pC, *pWp;
    cudaGetSymbolAddress((void**)&pX,  g_X);
    cudaGetSymbolAddress((void**)&pH1, g_H1);
    cudaGetSymbolAddress((void**)&pH2, g_H2);
    cudaGetSymbolAddress((void**)&pC,  g_C);
    cudaGetSymbolAddress((void**)&pWp, g_Wp);

    // Phase P: repack recurrent weights into coalesced layout
    struct PW { int idx, off, nout, K; };
    const PW pw[14] = {
        { 6, OFF_FW,  64, 388}, { 7, OFF_FWG, 64,  64},
        { 8, OFF_IH1, 192, 128}, { 9, OFF_HH1, 192, 64},
        {10, OFF_IH2, 192, 128}, {11, OFF_HH2, 192, 64},
        {12, OFF_IH3, 192, 128}, {13, OFF_HH3, 192, 64},
        {14, OFF_G1,  64,  64}, {15, OFF_G2,  64,  64}, {16, OFF_G3, 64, 64},
        {17, OFF_SG, 128, 128}, {18, OFF_SD, 128, 320}, {19, OFF_OUT, 64, 128},
    };
    for (int i = 0; i < 14; i++) {
        int n = pw[i].nout * pw[i].K;
        pack_w_kernel<<<(n + 255) / 256, 256>>>((const float*)d_in[pw[i].idx],
                                                pWp + pw[i].off,
                                                pw[i].nout, pw[i].K);
    }

    // Phase A: frame-feature conv stack (not recurrent)
    pack_kernel<<<6400, 256>>>(features, gfeat);
    gemm_nt_tanh<<<dim3(4, 100), 256>>>(pX,  Wc1, pH1, 6400, 256, 256);
    gemm_nt_tanh<<<dim3(4, 100), 256>>>(pH1, Wc2, pH2, 6400, 256, 256);
    gemm_nt_tanh<<<dim3(8, 100), 256>>>(pH2, Wc3, pC,  6400, 512, 256);

    // Phase B: persistent recurrent kernel (1 batch chain per CTA)
    static const int SMEM_BYTES = (int)sizeof(SM);
    cudaFuncSetAttribute(recur_kernel,
                         cudaFuncAttributeMaxDynamicSharedMemorySize, SMEM_BYTES);
    recur_kernel<<<64, 512, SMEM_BYTES>>>(prev, pWp, out);
}